// round 11
// baseline (speedup 1.0000x reference)
#include <cuda_runtime.h>

#define BB    16
#define NN    4096
#define CC    64
#define KNNK  32
#define QB    128
#define NPAIRS 2048                      // all 4096 candidates resident
#define CAP   320

#define F_INF  __int_as_float(0x7f800000)
#define F_NINF __int_as_float(0xff800000)
#define FULL   0xFFFFFFFFu

typedef unsigned long long ull;

// Scratch (static device globals — allowed; no runtime allocation).
__device__ int   g_idx[BB * NN * KNNK];      // 8 MB
__device__ float g_mx[BB * NN * CC];         // 16 MB
__device__ float g_mn[BB * NN * CC];         // 16 MB
__device__ float g_part[BB * NN / 8];        // 8192 block partials
__device__ float g_inv;

// ---- Blackwell packed f32x2 ops (PTX-only; min/max.f32x2 do NOT exist) ----
__device__ __forceinline__ ull fma2(ull a, ull b, ull c) {
    ull d; asm("fma.rn.f32x2 %0, %1, %2, %3;" : "=l"(d) : "l"(a), "l"(b), "l"(c));
    return d;
}
__device__ __forceinline__ ull mul2(ull a, ull b) {
    ull d; asm("mul.rn.f32x2 %0, %1, %2;" : "=l"(d) : "l"(a), "l"(b));
    return d;
}
__device__ __forceinline__ ull pk2(float lo, float hi) {
    ull r; asm("mov.b64 %0, {%1, %2};" : "=l"(r) : "f"(lo), "f"(hi));
    return r;
}
__device__ __forceinline__ void up2(ull v, float& lo, float& hi) {
    asm("mov.b64 {%0, %1}, %2;" : "=f"(lo), "=f"(hi) : "l"(v));
}

// Branchless insert into ascending sorted arrays (drop old max).
__device__ __forceinline__ void insert32(float (&sv)[KNNK], float c) {
#pragma unroll
    for (int u = 0; u < KNNK; u++) {
        float lo = fminf(sv[u], c);
        c = fmaxf(sv[u], c);
        sv[u] = lo;
    }
}
__device__ __forceinline__ void insert8(float (&s8)[8], float c) {
#pragma unroll
    for (int u = 0; u < 8; u++) {
        float lo = fminf(s8[u], c);
        c = fmaxf(s8[u], c);
        s8[u] = lo;
    }
}

// ---------------------------------------------------------------------------
// Kernel 1: exact 32-NN, one thread per query, all 4096 candidates in smem.
// Sampled static threshold (8th smallest of 256 samples, expected rank ~128)
// -> single flush-free sweep recording all d < t_est in index order
// -> exact 32nd ("w") from the record (record provably contains every
//    candidate < t_est, so if rc >= 32 its 32nd smallest == global 32nd)
// -> replay record for emission (jax lowest-index tie-break).
// Warp-uniform fallback to the R8 buffered/vote algorithm when any lane has
// rc < 32 or overflow (P ~ 7e-4 per thread).
// ---------------------------------------------------------------------------
__global__ void __launch_bounds__(QB, 4) knn_kernel(const float* __restrict__ xyz) {
    __shared__ ulonglong2 s_xy[NPAIRS];              // {x01, y01}  32 KB
    __shared__ ull        s_z [NPAIRS];              //  z01        16 KB

    const int b = blockIdx.x >> 5;                   // 32 blocks per batch
    const int i = ((blockIdx.x & 31) << 7) + threadIdx.x;
    const float* xb = xyz + (size_t)b * (3 * NN);

    // Load + pack all candidates.
    for (int p = threadIdx.x; p < NPAIRS; p += QB) {
        float2 X = *(const float2*)(xb + 2 * p);
        float2 Y = *(const float2*)(xb + NN + 2 * p);
        float2 Z = *(const float2*)(xb + 2 * NN + 2 * p);
        s_xy[p] = make_ulonglong2(pk2(X.x, X.y), pk2(Y.x, Y.y));
        s_z[p]  = pk2(Z.x, Z.y);
    }

    const float xi = xb[i], yi = xb[NN + i], zi = xb[2 * NN + i];
    const ull AX = pk2(-2.f * xi, -2.f * xi);
    const ull AY = pk2(-2.f * yi, -2.f * yi);
    const ull AZ = pk2(-2.f * zi, -2.f * zi);
    __syncthreads();

    // d_rel = ||xj||^2 - 2 xi.xj, rounding identical to R6/R8 champion.
    auto dist2 = [&](int p) -> ull {
        ulonglong2 XY = s_xy[p];
        ull Z  = s_z[p];
        ull nn = fma2(XY.x, XY.x, fma2(XY.y, XY.y, mul2(Z, Z)));
        return fma2(AX, XY.x, fma2(AY, XY.y, fma2(AZ, Z, nn)));
    };

    // ---- Phase 0: sampled threshold (256 candidates, sorted-8) -----------
    float s8[8];
#pragma unroll
    for (int u = 0; u < 8; u++) s8[u] = F_INF;
#pragma unroll 4
    for (int t = 0; t < 128; t++) {
        float d0, d1; up2(dist2(t * 16), d0, d1);
        insert8(s8, d0);
        insert8(s8, d1);
    }
    const float t_est = s8[7];

    // ---- Phase 1: flush-free sweep with static threshold -----------------
    float2 rec[CAP];                                 // local mem (d, idx-bits)
    int rc = 0;
    bool ofl = false;
#pragma unroll 4
    for (int p = 0; p < NPAIRS; p++) {
        float d0, d1; up2(dist2(p), d0, d1);
        if (d0 < t_est) {
            if (rc < CAP) rec[rc++] = make_float2(d0, __int_as_float(2 * p));
            else ofl = true;
        }
        if (d1 < t_est) {
            if (rc < CAP) rec[rc++] = make_float2(d1, __int_as_float(2 * p + 1));
            else ofl = true;
        }
    }

    const int base = (b * NN + i) * KNNK;
    const bool bad = ofl | (rc < KNNK);

    if (!__any_sync(FULL, bad)) {
        // ---- Phase 2 (fast, whole warp): exact select from record --------
        float sv[KNNK];
#pragma unroll
        for (int u = 0; u < KNNK; u++) sv[u] = F_INF;
        for (int t = 0; t < rc; t++) insert32(sv, rec[t].x);

        const float w = sv[KNNK - 1];                // exact global 32nd
        int ties = 1;
#pragma unroll
        for (int u = 0; u < KNNK - 1; u++) ties += (sv[u] == w);

        int cnt2 = 0;
        for (int t = 0; t < rc; t++) {
            float2 r = rec[t];
            bool lt = r.x < w;
            bool eq = (r.x == w);
            if (lt | (eq & (ties > 0))) {
                g_idx[base + cnt2] = __float_as_int(r.y);
                cnt2++;
                ties -= eq ? 1 : 0;
            }
        }
    } else {
        // ---- Fallback (warp-uniform, rare): R8 buffered/vote algorithm ---
        rc = 0; ofl = false;
        float sv[KNNK];
#pragma unroll
        for (int p = 0; p < KNNK / 2; p++) {         // warm-up: first 32
            float d0, d1; up2(dist2(p), d0, d1);
            sv[2 * p] = d0;
            sv[2 * p + 1] = d1;
            rec[rc++] = make_float2(d0, __int_as_float(2 * p));
            rec[rc++] = make_float2(d1, __int_as_float(2 * p + 1));
        }
#pragma unroll
        for (int k = 2; k <= KNNK; k <<= 1) {        // bitonic sort ascending
#pragma unroll
            for (int j = k >> 1; j > 0; j >>= 1) {
#pragma unroll
                for (int u = 0; u < KNNK; u++) {
                    int l = u ^ j;
                    if (l > u) {
                        bool up = ((u & k) == 0);
                        float lo = fminf(sv[u], sv[l]);
                        float hi = fmaxf(sv[u], sv[l]);
                        sv[u] = up ? lo : hi;
                        sv[l] = up ? hi : lo;
                    }
                }
            }
        }
        float worst = sv[KNNK - 1];

        float b0 = F_INF, b1 = F_INF, b2 = F_INF, b3 = F_INF;
        int cnt = 0;
        for (int p = KNNK / 2; p < NPAIRS; p++) {
            float d0, d1; up2(dist2(p), d0, d1);
            bool a0 = d0 < worst;
            bool a1 = d1 < worst;
            if (a0) {
                b3 = b2; b2 = b1; b1 = b0; b0 = d0; cnt++;
                if (rc < CAP) rec[rc++] = make_float2(d0, __int_as_float(2 * p));
                else ofl = true;
            }
            if (a1) {
                b3 = b2; b2 = b1; b1 = b0; b0 = d1; cnt++;
                if (rc < CAP) rec[rc++] = make_float2(d1, __int_as_float(2 * p + 1));
                else ofl = true;
            }
            if (__any_sync(FULL, cnt >= 3)) {
                insert32(sv, b0); insert32(sv, b1);
                insert32(sv, b2); insert32(sv, b3);
                b0 = b1 = b2 = b3 = F_INF; cnt = 0;
                worst = sv[KNNK - 1];
            }
        }
        insert32(sv, b0); insert32(sv, b1); insert32(sv, b2); insert32(sv, b3);

        const float w = sv[KNNK - 1];
        int ties = 1;
#pragma unroll
        for (int u = 0; u < KNNK - 1; u++) ties += (sv[u] == w);

        if (!ofl) {
            int cnt2 = 0;
            for (int t = 0; t < rc; t++) {
                float2 r = rec[t];
                bool lt = r.x < w;
                bool eq = (r.x == w);
                if (lt | (eq & (ties > 0))) {
                    g_idx[base + cnt2] = __float_as_int(r.y);
                    cnt2++;
                    ties -= eq ? 1 : 0;
                }
            }
        } else {
            int cnt2 = 0;                            // paranoia: rescan smem
            for (int p = 0; p < NPAIRS; p++) {
                float d0, d1; up2(dist2(p), d0, d1);
                bool lt0 = d0 < w, eq0 = (d0 == w);
                bool lt1 = d1 < w, eq1 = (d1 == w);
                if (lt0 | (eq0 & (ties > 0))) {
                    g_idx[base + cnt2] = 2 * p;
                    cnt2++;
                    ties -= eq0 ? 1 : 0;
                }
                if (lt1 | (eq1 & (ties > 0))) {
                    g_idx[base + cnt2] = 2 * p + 1;
                    cnt2++;
                    ties -= eq1 ? 1 : 0;
                }
            }
        }
    }
}

// ---------------------------------------------------------------------------
// Kernel 2: warp per (b,i). Lane = channel pair. Coalesced 256B row gathers.
// Produces per-channel max/min of offsets + block partial of sum(offset^2).
// ---------------------------------------------------------------------------
__global__ void __launch_bounds__(256) gather_kernel(const float* __restrict__ feats) {
    const int gw   = (blockIdx.x << 3) + (threadIdx.x >> 5);   // b*NN + i
    const int lane = threadIdx.x & 31;
    const int b = gw >> 12;
    const int i = gw & (NN - 1);
    const float* fb = feats + ((size_t)b << 18);               // b*NN*CC

    const float2 ctr = *(const float2*)(fb + i * CC + lane * 2);
    const int myid = g_idx[gw * KNNK + lane];

    float mx0 = F_NINF, mx1 = F_NINF;
    float mn0 = F_INF,  mn1 = F_INF;
    float ss = 0.f;

#pragma unroll
    for (int k = 0; k < KNNK; k++) {
        int j = __shfl_sync(FULL, myid, k);
        float2 f = *(const float2*)(fb + j * CC + lane * 2);
        float o0 = f.x - ctr.x, o1 = f.y - ctr.y;
        mx0 = fmaxf(mx0, o0); mn0 = fminf(mn0, o0);
        mx1 = fmaxf(mx1, o1); mn1 = fminf(mn1, o1);
        ss = fmaf(o0, o0, ss);
        ss = fmaf(o1, o1, ss);
    }

    const int ob = gw * CC + lane * 2;
    *(float2*)(g_mx + ob) = make_float2(mx0, mx1);
    *(float2*)(g_mn + ob) = make_float2(mn0, mn1);

#pragma unroll
    for (int off = 16; off; off >>= 1)
        ss += __shfl_xor_sync(FULL, ss, off);

    __shared__ float bs[8];
    if (lane == 0) bs[threadIdx.x >> 5] = ss;
    __syncthreads();
    if (threadIdx.x == 0) {
        g_part[blockIdx.x] = bs[0] + bs[1] + bs[2] + bs[3] +
                             bs[4] + bs[5] + bs[6] + bs[7];
    }
}

// ---------------------------------------------------------------------------
// Kernel 3: reduce partials -> g_inv = 1/(sigma + eps)
// ---------------------------------------------------------------------------
__global__ void reduce_kernel() {
    __shared__ float sm[256];
    float sacc = 0.f;
    for (int t = threadIdx.x; t < BB * NN / 8; t += 256) sacc += g_part[t];
    sm[threadIdx.x] = sacc;
    __syncthreads();
#pragma unroll
    for (int o = 128; o; o >>= 1) {
        if (threadIdx.x < o) sm[threadIdx.x] += sm[threadIdx.x + o];
        __syncthreads();
    }
    if (threadIdx.x == 0) {
        float sigma = sm[0] / (float)((long long)BB * NN * KNNK * CC);
        g_inv = 1.f / (sigma + 1e-5f);
    }
}

// ---------------------------------------------------------------------------
// Kernel 4: pooled = select(alpha>=0, max, min) * inv * alpha + beta
// (max over k commutes with the positive/negative scale)
// ---------------------------------------------------------------------------
__global__ void __launch_bounds__(256) final_kernel(const float* __restrict__ alpha,
                                                    const float* __restrict__ beta,
                                                    float* __restrict__ out) {
    const int idx = blockIdx.x * 256 + threadIdx.x;   // float2 index, 2M total
    const float inv = g_inv;
    const int c2 = idx & (CC / 2 - 1);
    const float a0 = alpha[c2 * 2], a1 = alpha[c2 * 2 + 1];
    const float b0 = beta[c2 * 2],  b1 = beta[c2 * 2 + 1];
    const float2 mx = ((const float2*)g_mx)[idx];
    const float2 mn = ((const float2*)g_mn)[idx];
    float v0 = (a0 >= 0.f) ? mx.x : mn.x;
    float v1 = (a1 >= 0.f) ? mx.y : mn.y;
    float2 r;
    r.x = fmaf(v0 * inv, a0, b0);
    r.y = fmaf(v1 * inv, a1, b1);
    ((float2*)out)[idx] = r;
}

extern "C" void kernel_launch(void* const* d_in, const int* in_sizes, int n_in,
                              void* d_out, int out_size) {
    const float* xyz   = (const float*)d_in[0];
    const float* feats = (const float*)d_in[1];
    const float* alpha = (const float*)d_in[2];
    const float* beta  = (const float*)d_in[3];
    float* out = (float*)d_out;
    (void)in_sizes; (void)n_in; (void)out_size;

    knn_kernel<<<BB * NN / QB, QB>>>(xyz);
    gather_kernel<<<BB * NN / 8, 256>>>(feats);
    reduce_kernel<<<1, 256>>>();
    final_kernel<<<BB * NN * CC / 512, 256>>>(alpha, beta, out);
}

// round 12
// speedup vs baseline: 1.1160x; 1.1160x over previous
#include <cuda_runtime.h>

#define BB    16
#define NN    4096
#define CC    64
#define KNNK  32
#define QB    128
#define NPAIRS 2048                      // all 4096 candidates resident
#define CAP   320

#define F_INF  __int_as_float(0x7f800000)
#define F_NINF __int_as_float(0xff800000)
#define FULL   0xFFFFFFFFu

typedef unsigned long long ull;

// Scratch (static device globals — allowed; no runtime allocation).
__device__ int   g_idx[BB * NN * KNNK];      // 8 MB
__device__ float g_mx[BB * NN * CC];         // 16 MB
__device__ float g_mn[BB * NN * CC];         // 16 MB
__device__ float g_part[BB * NN / 8];        // 8192 block partials
__device__ float g_inv;

// ---- Blackwell packed f32x2 ops (PTX-only; min/max.f32x2 do NOT exist) ----
__device__ __forceinline__ ull fma2(ull a, ull b, ull c) {
    ull d; asm("fma.rn.f32x2 %0, %1, %2, %3;" : "=l"(d) : "l"(a), "l"(b), "l"(c));
    return d;
}
__device__ __forceinline__ ull mul2(ull a, ull b) {
    ull d; asm("mul.rn.f32x2 %0, %1, %2;" : "=l"(d) : "l"(a), "l"(b));
    return d;
}
__device__ __forceinline__ ull pk2(float lo, float hi) {
    ull r; asm("mov.b64 %0, {%1, %2};" : "=l"(r) : "f"(lo), "f"(hi));
    return r;
}
__device__ __forceinline__ void up2(ull v, float& lo, float& hi) {
    asm("mov.b64 {%0, %1}, %2;" : "=f"(lo), "=f"(hi) : "l"(v));
}

// Branchless insert of c into ascending sorted 32-reg array (drops old max).
__device__ __forceinline__ void insert32(float (&sv)[KNNK], float c) {
#pragma unroll
    for (int u = 0; u < KNNK; u++) {
        float lo = fminf(sv[u], c);
        c = fmaxf(sv[u], c);
        sv[u] = lo;
    }
}

// Dummy no-op kernels: rotate ncu's "-s 5 -c 1" capture slot onto knn_kernel.
__global__ void nop_kernel() {}

// ---------------------------------------------------------------------------
// Kernel 1: exact 32-NN, one thread per query. All 4096 candidates resident
// in 48 KB smem. Bitonic warm-up seeds the sorted top-32; sweep with buffered
// accepts + warp-synchronized flush (__any vote). Accepted candidate INDICES
// recorded as u16 (local traffic 4x smaller than (d,idx) float2 — prime
// suspect for the unmodeled ~300us); replay recomputes distances from smem
// (bit-identical). Per-thread rescan fallback on overflow.
// ---------------------------------------------------------------------------
__global__ void __launch_bounds__(QB) knn_kernel(const float* __restrict__ xyz) {
    __shared__ ulonglong2 s_xy[NPAIRS];              // {x01, y01}  32 KB
    __shared__ ull        s_z [NPAIRS];              //  z01        16 KB

    const int b = blockIdx.x >> 5;                   // 32 blocks per batch
    const int i = ((blockIdx.x & 31) << 7) + threadIdx.x;
    const float* xb = xyz + (size_t)b * (3 * NN);

    // Load + pack all candidates.
    for (int p = threadIdx.x; p < NPAIRS; p += QB) {
        float2 X = *(const float2*)(xb + 2 * p);
        float2 Y = *(const float2*)(xb + NN + 2 * p);
        float2 Z = *(const float2*)(xb + 2 * NN + 2 * p);
        s_xy[p] = make_ulonglong2(pk2(X.x, X.y), pk2(Y.x, Y.y));
        s_z[p]  = pk2(Z.x, Z.y);
    }

    const float xi = xb[i], yi = xb[NN + i], zi = xb[2 * NN + i];
    const ull AX = pk2(-2.f * xi, -2.f * xi);
    const ull AY = pk2(-2.f * yi, -2.f * yi);
    const ull AZ = pk2(-2.f * zi, -2.f * zi);
    __syncthreads();

    // d_rel = ||xj||^2 - 2 xi.xj, rounding identical to the R6/R8 champion.
    auto dist2 = [&](int p) -> ull {
        ulonglong2 XY = s_xy[p];
        ull Z  = s_z[p];
        ull nn = fma2(XY.x, XY.x, fma2(XY.y, XY.y, mul2(Z, Z)));
        return fma2(AX, XY.x, fma2(AY, XY.y, fma2(AZ, Z, nn)));
    };

    unsigned short rec[CAP];                         // local mem, idx only
    int rc = 0;
    bool ofl = false;

    float sv[KNNK];
    // ---- warm-up: first 32 candidates seed sv via bitonic sort ----------
#pragma unroll
    for (int p = 0; p < KNNK / 2; p++) {
        float d0, d1; up2(dist2(p), d0, d1);
        sv[2 * p] = d0;
        sv[2 * p + 1] = d1;
        rec[rc++] = (unsigned short)(2 * p);
        rec[rc++] = (unsigned short)(2 * p + 1);
    }
#pragma unroll
    for (int k = 2; k <= KNNK; k <<= 1) {
#pragma unroll
        for (int j = k >> 1; j > 0; j >>= 1) {
#pragma unroll
            for (int u = 0; u < KNNK; u++) {
                int l = u ^ j;
                if (l > u) {
                    bool up = ((u & k) == 0);
                    float lo = fminf(sv[u], sv[l]);
                    float hi = fmaxf(sv[u], sv[l]);
                    sv[u] = up ? lo : hi;
                    sv[l] = up ? hi : lo;
                }
            }
        }
    }
    float worst = sv[KNNK - 1];

    // ---- sweep: buffered accepts, warp-synchronized flush ----------------
    float b0 = F_INF, b1 = F_INF, b2 = F_INF, b3 = F_INF;
    int cnt = 0;
#pragma unroll 4
    for (int p = KNNK / 2; p < NPAIRS; p++) {
        float d0, d1; up2(dist2(p), d0, d1);
        bool a0 = d0 < worst;
        bool a1 = d1 < worst;
        if (a0) {
            b3 = b2; b2 = b1; b1 = b0; b0 = d0; cnt++;
            if (rc < CAP) rec[rc++] = (unsigned short)(2 * p);
            else ofl = true;
        }
        if (a1) {
            b3 = b2; b2 = b1; b1 = b0; b0 = d1; cnt++;
            if (rc < CAP) rec[rc++] = (unsigned short)(2 * p + 1);
            else ofl = true;
        }
        if (__any_sync(FULL, cnt >= 3)) {
            insert32(sv, b0); insert32(sv, b1);
            insert32(sv, b2); insert32(sv, b3);
            b0 = b1 = b2 = b3 = F_INF; cnt = 0;
            worst = sv[KNNK - 1];
        }
    }
    insert32(sv, b0); insert32(sv, b1); insert32(sv, b2); insert32(sv, b3);

    const float w = sv[KNNK - 1];                    // exact 32nd smallest
    int ties = 1;                                    // emissions allowed at ==w
#pragma unroll
    for (int u = 0; u < KNNK - 1; u++) ties += (sv[u] == w);

    const int base = (b * NN + i) * KNNK;
    if (!ofl) {
        // ---- fast path: replay record, recomputing distances from smem --
        int cnt2 = 0;
        for (int t = 0; t < rc; t++) {
            int j = rec[t];
            float d0, d1; up2(dist2(j >> 1), d0, d1);
            float d = (j & 1) ? d1 : d0;
            bool lt = d < w;
            bool eq = (d == w);
            if (lt | (eq & (ties > 0))) {
                g_idx[base + cnt2] = j;
                cnt2++;
                ties -= eq ? 1 : 0;
            }
        }
    } else {
        // ---- fallback (never expected): rescan resident candidates ------
        int cnt2 = 0;
        for (int p = 0; p < NPAIRS; p++) {
            float d0, d1; up2(dist2(p), d0, d1);
            bool lt0 = d0 < w, eq0 = (d0 == w);
            bool lt1 = d1 < w, eq1 = (d1 == w);
            if (lt0 | (eq0 & (ties > 0))) {
                g_idx[base + cnt2] = 2 * p;
                cnt2++;
                ties -= eq0 ? 1 : 0;
            }
            if (lt1 | (eq1 & (ties > 0))) {
                g_idx[base + cnt2] = 2 * p + 1;
                cnt2++;
                ties -= eq1 ? 1 : 0;
            }
        }
    }
}

// ---------------------------------------------------------------------------
// Kernel 2: warp per (b,i). Lane = channel pair. Coalesced 256B row gathers.
// Produces per-channel max/min of offsets + block partial of sum(offset^2).
// ---------------------------------------------------------------------------
__global__ void __launch_bounds__(256) gather_kernel(const float* __restrict__ feats) {
    const int gw   = (blockIdx.x << 3) + (threadIdx.x >> 5);   // b*NN + i
    const int lane = threadIdx.x & 31;
    const int b = gw >> 12;
    const int i = gw & (NN - 1);
    const float* fb = feats + ((size_t)b << 18);               // b*NN*CC

    const float2 ctr = *(const float2*)(fb + i * CC + lane * 2);
    const int myid = g_idx[gw * KNNK + lane];

    float mx0 = F_NINF, mx1 = F_NINF;
    float mn0 = F_INF,  mn1 = F_INF;
    float ss = 0.f;

#pragma unroll
    for (int k = 0; k < KNNK; k++) {
        int j = __shfl_sync(FULL, myid, k);
        float2 f = *(const float2*)(fb + j * CC + lane * 2);
        float o0 = f.x - ctr.x, o1 = f.y - ctr.y;
        mx0 = fmaxf(mx0, o0); mn0 = fminf(mn0, o0);
        mx1 = fmaxf(mx1, o1); mn1 = fminf(mn1, o1);
        ss = fmaf(o0, o0, ss);
        ss = fmaf(o1, o1, ss);
    }

    const int ob = gw * CC + lane * 2;
    *(float2*)(g_mx + ob) = make_float2(mx0, mx1);
    *(float2*)(g_mn + ob) = make_float2(mn0, mn1);

#pragma unroll
    for (int off = 16; off; off >>= 1)
        ss += __shfl_xor_sync(FULL, ss, off);

    __shared__ float bs[8];
    if (lane == 0) bs[threadIdx.x >> 5] = ss;
    __syncthreads();
    if (threadIdx.x == 0) {
        g_part[blockIdx.x] = bs[0] + bs[1] + bs[2] + bs[3] +
                             bs[4] + bs[5] + bs[6] + bs[7];
    }
}

// ---------------------------------------------------------------------------
// Kernel 3: reduce partials -> g_inv = 1/(sigma + eps)
// ---------------------------------------------------------------------------
__global__ void reduce_kernel() {
    __shared__ float sm[256];
    float sacc = 0.f;
    for (int t = threadIdx.x; t < BB * NN / 8; t += 256) sacc += g_part[t];
    sm[threadIdx.x] = sacc;
    __syncthreads();
#pragma unroll
    for (int o = 128; o; o >>= 1) {
        if (threadIdx.x < o) sm[threadIdx.x] += sm[threadIdx.x + o];
        __syncthreads();
    }
    if (threadIdx.x == 0) {
        float sigma = sm[0] / (float)((long long)BB * NN * KNNK * CC);
        g_inv = 1.f / (sigma + 1e-5f);
    }
}

// ---------------------------------------------------------------------------
// Kernel 4: pooled = select(alpha>=0, max, min) * inv * alpha + beta
// (max over k commutes with the positive/negative scale)
// ---------------------------------------------------------------------------
__global__ void __launch_bounds__(256) final_kernel(const float* __restrict__ alpha,
                                                    const float* __restrict__ beta,
                                                    float* __restrict__ out) {
    const int idx = blockIdx.x * 256 + threadIdx.x;   // float2 index, 2M total
    const float inv = g_inv;
    const int c2 = idx & (CC / 2 - 1);
    const float a0 = alpha[c2 * 2], a1 = alpha[c2 * 2 + 1];
    const float b0 = beta[c2 * 2],  b1 = beta[c2 * 2 + 1];
    const float2 mx = ((const float2*)g_mx)[idx];
    const float2 mn = ((const float2*)g_mn)[idx];
    float v0 = (a0 >= 0.f) ? mx.x : mn.x;
    float v1 = (a1 >= 0.f) ? mx.y : mn.y;
    float2 r;
    r.x = fmaf(v0 * inv, a0, b0);
    r.y = fmaf(v1 * inv, a1, b1);
    ((float2*)out)[idx] = r;
}

extern "C" void kernel_launch(void* const* d_in, const int* in_sizes, int n_in,
                              void* d_out, int out_size) {
    const float* xyz   = (const float*)d_in[0];
    const float* feats = (const float*)d_in[1];
    const float* alpha = (const float*)d_in[2];
    const float* beta  = (const float*)d_in[3];
    float* out = (float*)d_out;
    (void)in_sizes; (void)n_in; (void)out_size;

    // Rotate ncu's skip-5 capture window onto knn_kernel (~3us overhead).
    nop_kernel<<<1, 1>>>();
    nop_kernel<<<1, 1>>>();
    nop_kernel<<<1, 1>>>();

    knn_kernel<<<BB * NN / QB, QB>>>(xyz);
    gather_kernel<<<BB * NN / 8, 256>>>(feats);
    reduce_kernel<<<1, 256>>>();
    final_kernel<<<BB * NN * CC / 512, 256>>>(alpha, beta, out);
}

// round 13
// speedup vs baseline: 1.1866x; 1.0632x over previous
#include <cuda_runtime.h>

#define BB    16
#define NN    4096
#define CC    64
#define KNNK  32
#define QB    128
#define NPAIRS 2048                      // all 4096 candidates resident
#define CAP   320

#define F_INF  __int_as_float(0x7f800000)
#define F_NINF __int_as_float(0xff800000)
#define FULL   0xFFFFFFFFu

typedef unsigned long long ull;

// Scratch (static device globals — allowed; no runtime allocation).
__device__ int   g_idx[BB * NN * KNNK];      // 8 MB
__device__ float g_mx[BB * NN * CC];         // 16 MB
__device__ float g_mn[BB * NN * CC];         // 16 MB
__device__ float g_part[BB * NN / 8];        // 8192 block partials
__device__ float g_inv;

// ---- Blackwell packed f32x2 ops (PTX-only; min/max.f32x2 do NOT exist) ----
__device__ __forceinline__ ull fma2(ull a, ull b, ull c) {
    ull d; asm("fma.rn.f32x2 %0, %1, %2, %3;" : "=l"(d) : "l"(a), "l"(b), "l"(c));
    return d;
}
__device__ __forceinline__ ull mul2(ull a, ull b) {
    ull d; asm("mul.rn.f32x2 %0, %1, %2;" : "=l"(d) : "l"(a), "l"(b));
    return d;
}
__device__ __forceinline__ ull pk2(float lo, float hi) {
    ull r; asm("mov.b64 %0, {%1, %2};" : "=l"(r) : "f"(lo), "f"(hi));
    return r;
}
__device__ __forceinline__ void up2(ull v, float& lo, float& hi) {
    asm("mov.b64 {%0, %1}, %2;" : "=f"(lo), "=f"(hi) : "l"(v));
}

// Software-pipelined insertion of FOUR values into the ascending sorted
// 32-reg array. Identical op pairs / per-element order as four sequential
// insert32 calls (bit-identical result), but scheduled as 35 phases of up
// to 8 INDEPENDENT FMNMX — ILP 8 instead of a serial 512-cycle chain.
// (R12 ncu: FMNMX is ALU-pipe; flush serialization capped issue at 56%.)
__device__ __forceinline__ void insert32x4(float (&sv)[KNNK],
                                           float c0, float c1,
                                           float c2, float c3) {
#pragma unroll
    for (int t = 0; t < KNNK + 3; t++) {
        if (t < KNNK) {
            float lo = fminf(sv[t], c0); c0 = fmaxf(sv[t], c0); sv[t] = lo;
        }
        if (t >= 1 && t - 1 < KNNK) {
            float lo = fminf(sv[t-1], c1); c1 = fmaxf(sv[t-1], c1); sv[t-1] = lo;
        }
        if (t >= 2 && t - 2 < KNNK) {
            float lo = fminf(sv[t-2], c2); c2 = fmaxf(sv[t-2], c2); sv[t-2] = lo;
        }
        if (t >= 3 && t - 3 < KNNK) {
            float lo = fminf(sv[t-3], c3); c3 = fmaxf(sv[t-3], c3); sv[t-3] = lo;
        }
    }
}

// Dummy no-op kernels: rotate ncu's "-s 5 -c 1" capture slot onto knn_kernel.
__global__ void nop_kernel() {}

// ---------------------------------------------------------------------------
// Kernel 1: exact 32-NN, one thread per query. All 4096 candidates resident
// in 48 KB smem. Bitonic warm-up seeds the sorted top-32; sweep with buffered
// accepts + warp-synchronized flush (__any vote) using the PIPELINED
// insert32x4. Accepted (d, idx) recorded to local mem in index order and
// replayed for emission. Per-thread rescan fallback on overflow.
// ---------------------------------------------------------------------------
__global__ void __launch_bounds__(QB) knn_kernel(const float* __restrict__ xyz) {
    __shared__ ulonglong2 s_xy[NPAIRS];              // {x01, y01}  32 KB
    __shared__ ull        s_z [NPAIRS];              //  z01        16 KB

    const int b = blockIdx.x >> 5;                   // 32 blocks per batch
    const int i = ((blockIdx.x & 31) << 7) + threadIdx.x;
    const float* xb = xyz + (size_t)b * (3 * NN);

    // Load + pack all candidates.
    for (int p = threadIdx.x; p < NPAIRS; p += QB) {
        float2 X = *(const float2*)(xb + 2 * p);
        float2 Y = *(const float2*)(xb + NN + 2 * p);
        float2 Z = *(const float2*)(xb + 2 * NN + 2 * p);
        s_xy[p] = make_ulonglong2(pk2(X.x, X.y), pk2(Y.x, Y.y));
        s_z[p]  = pk2(Z.x, Z.y);
    }

    const float xi = xb[i], yi = xb[NN + i], zi = xb[2 * NN + i];
    const ull AX = pk2(-2.f * xi, -2.f * xi);
    const ull AY = pk2(-2.f * yi, -2.f * yi);
    const ull AZ = pk2(-2.f * zi, -2.f * zi);
    __syncthreads();

    // d_rel = ||xj||^2 - 2 xi.xj, rounding identical to the R6/R8 champion.
    auto dist2 = [&](int p) -> ull {
        ulonglong2 XY = s_xy[p];
        ull Z  = s_z[p];
        ull nn = fma2(XY.x, XY.x, fma2(XY.y, XY.y, mul2(Z, Z)));
        return fma2(AX, XY.x, fma2(AY, XY.y, fma2(AZ, Z, nn)));
    };

    float2 rec[CAP];                                 // local mem (d, idx-bits)
    int rc = 0;
    bool ofl = false;

    float sv[KNNK];
    // ---- warm-up: first 32 candidates seed sv via bitonic sort ----------
#pragma unroll
    for (int p = 0; p < KNNK / 2; p++) {
        float d0, d1; up2(dist2(p), d0, d1);
        sv[2 * p] = d0;
        sv[2 * p + 1] = d1;
        rec[rc++] = make_float2(d0, __int_as_float(2 * p));
        rec[rc++] = make_float2(d1, __int_as_float(2 * p + 1));
    }
#pragma unroll
    for (int k = 2; k <= KNNK; k <<= 1) {
#pragma unroll
        for (int j = k >> 1; j > 0; j >>= 1) {
#pragma unroll
            for (int u = 0; u < KNNK; u++) {
                int l = u ^ j;
                if (l > u) {
                    bool up = ((u & k) == 0);
                    float lo = fminf(sv[u], sv[l]);
                    float hi = fmaxf(sv[u], sv[l]);
                    sv[u] = up ? lo : hi;
                    sv[l] = up ? hi : lo;
                }
            }
        }
    }
    float worst = sv[KNNK - 1];

    // ---- sweep: buffered accepts, warp-synchronized pipelined flush ------
    float b0 = F_INF, b1 = F_INF, b2 = F_INF, b3 = F_INF;
    int cnt = 0;
#pragma unroll 4
    for (int p = KNNK / 2; p < NPAIRS; p++) {
        float d0, d1; up2(dist2(p), d0, d1);
        bool a0 = d0 < worst;
        bool a1 = d1 < worst;
        if (a0) {
            b3 = b2; b2 = b1; b1 = b0; b0 = d0; cnt++;
            if (rc < CAP) rec[rc++] = make_float2(d0, __int_as_float(2 * p));
            else ofl = true;
        }
        if (a1) {
            b3 = b2; b2 = b1; b1 = b0; b0 = d1; cnt++;
            if (rc < CAP) rec[rc++] = make_float2(d1, __int_as_float(2 * p + 1));
            else ofl = true;
        }
        if (__any_sync(FULL, cnt >= 3)) {
            insert32x4(sv, b0, b1, b2, b3);
            b0 = b1 = b2 = b3 = F_INF; cnt = 0;
            worst = sv[KNNK - 1];
        }
    }
    insert32x4(sv, b0, b1, b2, b3);

    const float w = sv[KNNK - 1];                    // exact 32nd smallest
    int ties = 1;                                    // emissions allowed at ==w
#pragma unroll
    for (int u = 0; u < KNNK - 1; u++) ties += (sv[u] == w);

    const int base = (b * NN + i) * KNNK;
    if (!ofl) {
        // ---- fast path: replay recorded list -----------------------------
        int cnt2 = 0;
        for (int t = 0; t < rc; t++) {
            float2 r = rec[t];
            bool lt = r.x < w;
            bool eq = (r.x == w);
            if (lt | (eq & (ties > 0))) {
                g_idx[base + cnt2] = __float_as_int(r.y);
                cnt2++;
                ties -= eq ? 1 : 0;
            }
        }
    } else {
        // ---- fallback (never expected): rescan resident candidates ------
        int cnt2 = 0;
        for (int p = 0; p < NPAIRS; p++) {
            float d0, d1; up2(dist2(p), d0, d1);
            bool lt0 = d0 < w, eq0 = (d0 == w);
            bool lt1 = d1 < w, eq1 = (d1 == w);
            if (lt0 | (eq0 & (ties > 0))) {
                g_idx[base + cnt2] = 2 * p;
                cnt2++;
                ties -= eq0 ? 1 : 0;
            }
            if (lt1 | (eq1 & (ties > 0))) {
                g_idx[base + cnt2] = 2 * p + 1;
                cnt2++;
                ties -= eq1 ? 1 : 0;
            }
        }
    }
}

// ---------------------------------------------------------------------------
// Kernel 2: warp per (b,i). Lane = channel pair. Coalesced 256B row gathers.
// Produces per-channel max/min of offsets + block partial of sum(offset^2).
// ---------------------------------------------------------------------------
__global__ void __launch_bounds__(256) gather_kernel(const float* __restrict__ feats) {
    const int gw   = (blockIdx.x << 3) + (threadIdx.x >> 5);   // b*NN + i
    const int lane = threadIdx.x & 31;
    const int b = gw >> 12;
    const int i = gw & (NN - 1);
    const float* fb = feats + ((size_t)b << 18);               // b*NN*CC

    const float2 ctr = *(const float2*)(fb + i * CC + lane * 2);
    const int myid = g_idx[gw * KNNK + lane];

    float mx0 = F_NINF, mx1 = F_NINF;
    float mn0 = F_INF,  mn1 = F_INF;
    float ss = 0.f;

#pragma unroll
    for (int k = 0; k < KNNK; k++) {
        int j = __shfl_sync(FULL, myid, k);
        float2 f = *(const float2*)(fb + j * CC + lane * 2);
        float o0 = f.x - ctr.x, o1 = f.y - ctr.y;
        mx0 = fmaxf(mx0, o0); mn0 = fminf(mn0, o0);
        mx1 = fmaxf(mx1, o1); mn1 = fminf(mn1, o1);
        ss = fmaf(o0, o0, ss);
        ss = fmaf(o1, o1, ss);
    }

    const int ob = gw * CC + lane * 2;
    *(float2*)(g_mx + ob) = make_float2(mx0, mx1);
    *(float2*)(g_mn + ob) = make_float2(mn0, mn1);

#pragma unroll
    for (int off = 16; off; off >>= 1)
        ss += __shfl_xor_sync(FULL, ss, off);

    __shared__ float bs[8];
    if (lane == 0) bs[threadIdx.x >> 5] = ss;
    __syncthreads();
    if (threadIdx.x == 0) {
        g_part[blockIdx.x] = bs[0] + bs[1] + bs[2] + bs[3] +
                             bs[4] + bs[5] + bs[6] + bs[7];
    }
}

// ---------------------------------------------------------------------------
// Kernel 3: reduce partials -> g_inv = 1/(sigma + eps)
// ---------------------------------------------------------------------------
__global__ void reduce_kernel() {
    __shared__ float sm[256];
    float sacc = 0.f;
    for (int t = threadIdx.x; t < BB * NN / 8; t += 256) sacc += g_part[t];
    sm[threadIdx.x] = sacc;
    __syncthreads();
#pragma unroll
    for (int o = 128; o; o >>= 1) {
        if (threadIdx.x < o) sm[threadIdx.x] += sm[threadIdx.x + o];
        __syncthreads();
    }
    if (threadIdx.x == 0) {
        float sigma = sm[0] / (float)((long long)BB * NN * KNNK * CC);
        g_inv = 1.f / (sigma + 1e-5f);
    }
}

// ---------------------------------------------------------------------------
// Kernel 4: pooled = select(alpha>=0, max, min) * inv * alpha + beta
// (max over k commutes with the positive/negative scale)
// ---------------------------------------------------------------------------
__global__ void __launch_bounds__(256) final_kernel(const float* __restrict__ alpha,
                                                    const float* __restrict__ beta,
                                                    float* __restrict__ out) {
    const int idx = blockIdx.x * 256 + threadIdx.x;   // float2 index, 2M total
    const float inv = g_inv;
    const int c2 = idx & (CC / 2 - 1);
    const float a0 = alpha[c2 * 2], a1 = alpha[c2 * 2 + 1];
    const float b0 = beta[c2 * 2],  b1 = beta[c2 * 2 + 1];
    const float2 mx = ((const float2*)g_mx)[idx];
    const float2 mn = ((const float2*)g_mn)[idx];
    float v0 = (a0 >= 0.f) ? mx.x : mn.x;
    float v1 = (a1 >= 0.f) ? mx.y : mn.y;
    float2 r;
    r.x = fmaf(v0 * inv, a0, b0);
    r.y = fmaf(v1 * inv, a1, b1);
    ((float2*)out)[idx] = r;
}

extern "C" void kernel_launch(void* const* d_in, const int* in_sizes, int n_in,
                              void* d_out, int out_size) {
    const float* xyz   = (const float*)d_in[0];
    const float* feats = (const float*)d_in[1];
    const float* alpha = (const float*)d_in[2];
    const float* beta  = (const float*)d_in[3];
    float* out = (float*)d_out;
    (void)in_sizes; (void)n_in; (void)out_size;

    // Rotate ncu's skip-5 capture window onto knn_kernel (~3us overhead).
    nop_kernel<<<1, 1>>>();
    nop_kernel<<<1, 1>>>();
    nop_kernel<<<1, 1>>>();

    knn_kernel<<<BB * NN / QB, QB>>>(xyz);
    gather_kernel<<<BB * NN / 8, 256>>>(feats);
    reduce_kernel<<<1, 256>>>();
    final_kernel<<<BB * NN * CC / 512, 256>>>(alpha, beta, out);
}

// round 14
// speedup vs baseline: 1.4231x; 1.1994x over previous
#include <cuda_runtime.h>

#define BB    16
#define NN    4096
#define CC    64
#define KNNK  32
#define QB    128
#define NPAIRS 2048                      // all 4096 candidates resident
#define CAP   384

#define F_INF  __int_as_float(0x7f800000)
#define F_NINF __int_as_float(0xff800000)
#define FULL   0xFFFFFFFFu

typedef unsigned long long ull;

// Scratch (static device globals — allowed; no runtime allocation).
__device__ int   g_idx[BB * NN * KNNK];      // 8 MB
__device__ float g_mx[BB * NN * CC];         // 16 MB
__device__ float g_mn[BB * NN * CC];         // 16 MB
__device__ float g_part[BB * NN / 8];        // 8192 block partials
__device__ float g_inv;

// ---- Blackwell packed f32x2 ops (PTX-only; min/max.f32x2 do NOT exist) ----
__device__ __forceinline__ ull fma2(ull a, ull b, ull c) {
    ull d; asm("fma.rn.f32x2 %0, %1, %2, %3;" : "=l"(d) : "l"(a), "l"(b), "l"(c));
    return d;
}
__device__ __forceinline__ ull mul2(ull a, ull b) {
    ull d; asm("mul.rn.f32x2 %0, %1, %2;" : "=l"(d) : "l"(a), "l"(b));
    return d;
}
__device__ __forceinline__ ull pk2(float lo, float hi) {
    ull r; asm("mov.b64 %0, {%1, %2};" : "=l"(r) : "f"(lo), "f"(hi));
    return r;
}
__device__ __forceinline__ void up2(ull v, float& lo, float& hi) {
    asm("mov.b64 {%0, %1}, %2;" : "=f"(lo), "=f"(hi) : "l"(v));
}

// Branchless insert of c into ascending sorted 32-reg array (fallback only).
__device__ __forceinline__ void insert32(float (&sv)[KNNK], float c) {
#pragma unroll
    for (int u = 0; u < KNNK; u++) {
        float lo = fminf(sv[u], c);
        c = fmaxf(sv[u], c);
        sv[u] = lo;
    }
}

// Dummy no-op kernels: rotate ncu's "-s 5 -c 1" capture slot onto knn_kernel.
__global__ void nop_kernel() {}

// ---------------------------------------------------------------------------
// Kernel 1: exact 32-NN, one thread per query. All 4096 candidates resident
// in 48 KB smem. Batched selection: accepts append to the local record; when
// any lane has 31 buffered, flush = bitonic-sort the batch (ILP 16) +
// bitonic merge-keep-min-32 with sv. ~22 FMNMX/accept instead of 64
// (R13 ncu: ALU pipe = 45% of peak = 83% of issues; insertion cost is the
// algorithmic floor). sv=INF start makes the first flush the warm-up.
// Replay record for emission; per-thread full-recompute fallback on overflow.
// ---------------------------------------------------------------------------
__global__ void __launch_bounds__(QB) knn_kernel(const float* __restrict__ xyz) {
    __shared__ ulonglong2 s_xy[NPAIRS];              // {x01, y01}  32 KB
    __shared__ ull        s_z [NPAIRS];              //  z01        16 KB

    const int b = blockIdx.x >> 5;                   // 32 blocks per batch
    const int i = ((blockIdx.x & 31) << 7) + threadIdx.x;
    const float* xb = xyz + (size_t)b * (3 * NN);

    // Load + pack all candidates.
    for (int p = threadIdx.x; p < NPAIRS; p += QB) {
        float2 X = *(const float2*)(xb + 2 * p);
        float2 Y = *(const float2*)(xb + NN + 2 * p);
        float2 Z = *(const float2*)(xb + 2 * NN + 2 * p);
        s_xy[p] = make_ulonglong2(pk2(X.x, X.y), pk2(Y.x, Y.y));
        s_z[p]  = pk2(Z.x, Z.y);
    }

    const float xi = xb[i], yi = xb[NN + i], zi = xb[2 * NN + i];
    const ull AX = pk2(-2.f * xi, -2.f * xi);
    const ull AY = pk2(-2.f * yi, -2.f * yi);
    const ull AZ = pk2(-2.f * zi, -2.f * zi);
    __syncthreads();

    // d_rel = ||xj||^2 - 2 xi.xj, rounding identical to the R6/R8 champion.
    auto dist2 = [&](int p) -> ull {
        ulonglong2 XY = s_xy[p];
        ull Z  = s_z[p];
        ull nn = fma2(XY.x, XY.x, fma2(XY.y, XY.y, mul2(Z, Z)));
        return fma2(AX, XY.x, fma2(AY, XY.y, fma2(AZ, Z, nn)));
    };

    float2 rec[CAP];                                 // local mem (d, idx-bits)
    int rc = 0;                                      // total recorded
    int cnt = 0;                                     // recorded since flush
    bool ofl = false;

    float sv[KNNK];
#pragma unroll
    for (int u = 0; u < KNNK; u++) sv[u] = F_INF;
    float worst = F_INF;

    // Flush: exact top-32 update from the last `cnt` recorded distances.
    auto flush = [&]() {
        float t32[KNNK];
#pragma unroll
        for (int u = 0; u < KNNK; u++) {
            float v = F_INF;
            if (u < cnt) v = rec[rc - cnt + u].x;    // predicated LDL
            t32[u] = v;
        }
        // bitonic sort t32 ascending (ILP-16 network)
#pragma unroll
        for (int k = 2; k <= KNNK; k <<= 1) {
#pragma unroll
            for (int j = k >> 1; j > 0; j >>= 1) {
#pragma unroll
                for (int u = 0; u < KNNK; u++) {
                    int l = u ^ j;
                    if (l > u) {
                        bool up = ((u & k) == 0);
                        float lo = fminf(t32[u], t32[l]);
                        float hi = fmaxf(t32[u], t32[l]);
                        t32[u] = up ? lo : hi;
                        t32[l] = up ? hi : lo;
                    }
                }
            }
        }
        // keep-min-32 of sv ∪ t32: pairwise mins form a bitonic sequence
#pragma unroll
        for (int u = 0; u < KNNK; u++)
            sv[u] = fminf(sv[u], t32[KNNK - 1 - u]);
        // bitonic merge sv ascending (5 stages)
#pragma unroll
        for (int j = KNNK / 2; j > 0; j >>= 1) {
#pragma unroll
            for (int u = 0; u < KNNK; u++) {
                int l = u ^ j;
                if (l > u) {
                    float lo = fminf(sv[u], sv[l]);
                    float hi = fmaxf(sv[u], sv[l]);
                    sv[u] = lo; sv[l] = hi;
                }
            }
        }
        cnt = 0;
        worst = sv[KNNK - 1];
    };

    // ---- sweep all pairs: record accepts, batched flush -------------------
#pragma unroll 4
    for (int p = 0; p < NPAIRS; p++) {
        if (__any_sync(FULL, cnt >= 31)) flush();
        float d0, d1; up2(dist2(p), d0, d1);
        if (d0 < worst) {
            if (rc < CAP) { rec[rc++] = make_float2(d0, __int_as_float(2 * p)); cnt++; }
            else ofl = true;
        }
        if (d1 < worst) {
            if (rc < CAP) { rec[rc++] = make_float2(d1, __int_as_float(2 * p + 1)); cnt++; }
            else ofl = true;
        }
    }
    flush();                                         // leftovers

    float w = sv[KNNK - 1];                          // exact 32nd smallest
    int ties = 1;                                    // emissions allowed at ==w
#pragma unroll
    for (int u = 0; u < KNNK - 1; u++) ties += (sv[u] == w);

    const int base = (b * NN + i) * KNNK;
    if (!ofl) {
        // ---- fast path: replay recorded list -----------------------------
        int cnt2 = 0;
        for (int t = 0; t < rc; t++) {
            float2 r = rec[t];
            bool lt = r.x < w;
            bool eq = (r.x == w);
            if (lt | (eq & (ties > 0))) {
                g_idx[base + cnt2] = __float_as_int(r.y);
                cnt2++;
                ties -= eq ? 1 : 0;
            }
        }
    } else {
        // ---- fallback (never expected): full recompute + rescan ----------
#pragma unroll
        for (int u = 0; u < KNNK; u++) sv[u] = F_INF;
        for (int p = 0; p < NPAIRS; p++) {
            float d0, d1; up2(dist2(p), d0, d1);
            if (d0 < sv[KNNK - 1]) insert32(sv, d0);
            if (d1 < sv[KNNK - 1]) insert32(sv, d1);
        }
        w = sv[KNNK - 1];
        ties = 1;
#pragma unroll
        for (int u = 0; u < KNNK - 1; u++) ties += (sv[u] == w);
        int cnt2 = 0;
        for (int p = 0; p < NPAIRS; p++) {
            float d0, d1; up2(dist2(p), d0, d1);
            bool lt0 = d0 < w, eq0 = (d0 == w);
            bool lt1 = d1 < w, eq1 = (d1 == w);
            if (lt0 | (eq0 & (ties > 0))) {
                g_idx[base + cnt2] = 2 * p;
                cnt2++;
                ties -= eq0 ? 1 : 0;
            }
            if (lt1 | (eq1 & (ties > 0))) {
                g_idx[base + cnt2] = 2 * p + 1;
                cnt2++;
                ties -= eq1 ? 1 : 0;
            }
        }
    }
}

// ---------------------------------------------------------------------------
// Kernel 2: warp per (b,i). Lane = channel pair. Coalesced 256B row gathers.
// Produces per-channel max/min of offsets + block partial of sum(offset^2).
// ---------------------------------------------------------------------------
__global__ void __launch_bounds__(256) gather_kernel(const float* __restrict__ feats) {
    const int gw   = (blockIdx.x << 3) + (threadIdx.x >> 5);   // b*NN + i
    const int lane = threadIdx.x & 31;
    const int b = gw >> 12;
    const int i = gw & (NN - 1);
    const float* fb = feats + ((size_t)b << 18);               // b*NN*CC

    const float2 ctr = *(const float2*)(fb + i * CC + lane * 2);
    const int myid = g_idx[gw * KNNK + lane];

    float mx0 = F_NINF, mx1 = F_NINF;
    float mn0 = F_INF,  mn1 = F_INF;
    float ss = 0.f;

#pragma unroll
    for (int k = 0; k < KNNK; k++) {
        int j = __shfl_sync(FULL, myid, k);
        float2 f = *(const float2*)(fb + j * CC + lane * 2);
        float o0 = f.x - ctr.x, o1 = f.y - ctr.y;
        mx0 = fmaxf(mx0, o0); mn0 = fminf(mn0, o0);
        mx1 = fmaxf(mx1, o1); mn1 = fminf(mn1, o1);
        ss = fmaf(o0, o0, ss);
        ss = fmaf(o1, o1, ss);
    }

    const int ob = gw * CC + lane * 2;
    *(float2*)(g_mx + ob) = make_float2(mx0, mx1);
    *(float2*)(g_mn + ob) = make_float2(mn0, mn1);

#pragma unroll
    for (int off = 16; off; off >>= 1)
        ss += __shfl_xor_sync(FULL, ss, off);

    __shared__ float bs[8];
    if (lane == 0) bs[threadIdx.x >> 5] = ss;
    __syncthreads();
    if (threadIdx.x == 0) {
        g_part[blockIdx.x] = bs[0] + bs[1] + bs[2] + bs[3] +
                             bs[4] + bs[5] + bs[6] + bs[7];
    }
}

// ---------------------------------------------------------------------------
// Kernel 3: reduce partials -> g_inv = 1/(sigma + eps)
// ---------------------------------------------------------------------------
__global__ void reduce_kernel() {
    __shared__ float sm[256];
    float sacc = 0.f;
    for (int t = threadIdx.x; t < BB * NN / 8; t += 256) sacc += g_part[t];
    sm[threadIdx.x] = sacc;
    __syncthreads();
#pragma unroll
    for (int o = 128; o; o >>= 1) {
        if (threadIdx.x < o) sm[threadIdx.x] += sm[threadIdx.x + o];
        __syncthreads();
    }
    if (threadIdx.x == 0) {
        float sigma = sm[0] / (float)((long long)BB * NN * KNNK * CC);
        g_inv = 1.f / (sigma + 1e-5f);
    }
}

// ---------------------------------------------------------------------------
// Kernel 4: pooled = select(alpha>=0, max, min) * inv * alpha + beta
// (max over k commutes with the positive/negative scale)
// ---------------------------------------------------------------------------
__global__ void __launch_bounds__(256) final_kernel(const float* __restrict__ alpha,
                                                    const float* __restrict__ beta,
                                                    float* __restrict__ out) {
    const int idx = blockIdx.x * 256 + threadIdx.x;   // float2 index, 2M total
    const float inv = g_inv;
    const int c2 = idx & (CC / 2 - 1);
    const float a0 = alpha[c2 * 2], a1 = alpha[c2 * 2 + 1];
    const float b0 = beta[c2 * 2],  b1 = beta[c2 * 2 + 1];
    const float2 mx = ((const float2*)g_mx)[idx];
    const float2 mn = ((const float2*)g_mn)[idx];
    float v0 = (a0 >= 0.f) ? mx.x : mn.x;
    float v1 = (a1 >= 0.f) ? mx.y : mn.y;
    float2 r;
    r.x = fmaf(v0 * inv, a0, b0);
    r.y = fmaf(v1 * inv, a1, b1);
    ((float2*)out)[idx] = r;
}

extern "C" void kernel_launch(void* const* d_in, const int* in_sizes, int n_in,
                              void* d_out, int out_size) {
    const float* xyz   = (const float*)d_in[0];
    const float* feats = (const float*)d_in[1];
    const float* alpha = (const float*)d_in[2];
    const float* beta  = (const float*)d_in[3];
    float* out = (float*)d_out;
    (void)in_sizes; (void)n_in; (void)out_size;

    // Rotate ncu's skip-5 capture window onto knn_kernel (~3us overhead).
    nop_kernel<<<1, 1>>>();
    nop_kernel<<<1, 1>>>();
    nop_kernel<<<1, 1>>>();

    knn_kernel<<<BB * NN / QB, QB>>>(xyz);
    gather_kernel<<<BB * NN / 8, 256>>>(feats);
    reduce_kernel<<<1, 256>>>();
    final_kernel<<<BB * NN * CC / 512, 256>>>(alpha, beta, out);
}